// round 11
// baseline (speedup 1.0000x reference)
#include <cuda_runtime.h>
#include <cuda_fp16.h>
#include <cstdint>

#define D 128
#define NV_MAX 200000
#define NN_MAX 20000

typedef unsigned long long u64;
typedef unsigned int u32;

// ---------------- device scratch (no allocs allowed) ------------------------
__device__ __align__(16) unsigned char g_Ph[(size_t)NV_MAX * 256]; // P fp16 (51MB)
__device__ __align__(16) unsigned char g_Vh[(size_t)NV_MAX * 256]; // V fp16 (51MB)
__device__ __align__(16) unsigned char g_Qh[(size_t)NN_MAX * 256]; // Q fp16 (5MB)

// ---------------- smem layouts ------------------------------------------------
// proj (97KB -> 2 CTAs/SM)
#define PP_B0   0
#define PP_B1   32768
#define PP_A    65536
#define PP_BS   98304      // float b1 [128]
#define PP_SMEM 99328
// agg (~104KB -> 2 CTAs/SM)
#define AG_B    0          // B fp16 32K
#define AG_A    32768      // A fp16 32K (overlay: agg partials post-GEMM)
#define AG_PST  65536      // staged P fp16 rows, 272B stride (34816B)
#define AG_BW   100352     // float2 b2/W3 [128]          (1K)
#define AG_QST  101376     // uint4 q rows [2buf][64]     (2K)
#define AG_IDX  103424     // int [2buf][128]             (1K)
#define AG_SP   104448     // score partials float[2][128](1K)
#define AG_ATT  105472     // att float[128]              (512B)
#define AG_SMEM 105984

// ---------------- helpers ------------------------------------------------------
__device__ __forceinline__ u32 smem_u32(const void* p) {
    u32 a; asm("{ .reg .u64 t; cvta.to.shared.u64 t, %1; cvt.u32.u64 %0, t; }" : "=r"(a) : "l"(p));
    return a;
}
__device__ __forceinline__ void ldm_x4(u32 addr, u32* r) {
    asm volatile("ldmatrix.sync.aligned.m8n8.x4.shared.b16 {%0,%1,%2,%3}, [%4];"
        : "=r"(r[0]), "=r"(r[1]), "=r"(r[2]), "=r"(r[3]) : "r"(addr));
}
__device__ __forceinline__ void mma_f16(float* c, const u32* a, const u32* b) {
    asm volatile("mma.sync.aligned.m16n8k16.row.col.f32.f16.f16.f32 "
        "{%0,%1,%2,%3}, {%4,%5,%6,%7}, {%8,%9}, {%0,%1,%2,%3};"
        : "+f"(c[0]), "+f"(c[1]), "+f"(c[2]), "+f"(c[3])
        : "r"(a[0]), "r"(a[1]), "r"(a[2]), "r"(a[3]), "r"(b[0]), "r"(b[1]));
}
__device__ __forceinline__ void cpa16(u32 dst, const void* src) {
    asm volatile("cp.async.cg.shared.global [%0], [%1], 16;" :: "r"(dst), "l"(src) : "memory");
}
#define CP_COMMIT() asm volatile("cp.async.commit_group;" ::: "memory")
#define CP_WAIT0()  asm volatile("cp.async.wait_group 0;" ::: "memory")

__device__ __forceinline__ uint4 pack8h(float4 a, float4 b) {
    __half2 h0 = __floats2half2_rn(a.x, a.y);
    __half2 h1 = __floats2half2_rn(a.z, a.w);
    __half2 h2 = __floats2half2_rn(b.x, b.y);
    __half2 h3 = __floats2half2_rn(b.z, b.w);
    return make_uint4(*(u32*)&h0, *(u32*)&h1, *(u32*)&h2, *(u32*)&h3);
}
// relu(a + b) in packed half2 (u32-typed)
__device__ __forceinline__ u32 haddrelu2(u32 a, u32 b) {
    __half2 s = __hadd2(*(__half2*)&a, *(__half2*)&b);
    u32 zero = 0u;
    __half2 r = __hmax2(s, *(__half2*)&zero);
    return *(u32*)&r;
}
// stage a fp16 transposed+swizzled weight image from fp32 W[k*D+n]
__device__ __forceinline__ void build_wimg(char* dst, const float* __restrict__ W, int t) {
    int n = t & 127, kh = t >> 7;
    #pragma unroll 8
    for (int kk = 0; kk < 64; kk++) {
        int k = kh * 64 + kk;
        __half h = __float2half_rn(W[k * D + n]);
        int o = n * 256 + ((((k >> 3) ^ (n & 7))) << 4) + ((k & 7) << 1);
        *(__half*)(dst + o) = h;
    }
}

// ---------------- GEMM: block 128x128, warp 32x64, fp16 single-pass ------------
__device__ __forceinline__ void gemm32_1p(u32 sA, u32 sB, int lane, int mw, int nw,
                                          float (&acc)[2][8][4]) {
    const int lr   = lane & 7;
    const int akl  = lane >> 4;
    const int arow = lr + ((lane >> 3) & 1) * 8;
    const int bkl  = (lane >> 3) & 1;
    const int brow = lr + (lane >> 4) * 8;
    u32 aoffm[2];
    #pragma unroll
    for (int mt = 0; mt < 2; mt++) aoffm[mt] = (u32)((32 * mw + 16 * mt + arow) * 256);
    u32 boff[4];
    #pragma unroll
    for (int n2 = 0; n2 < 4; n2++) boff[n2] = (u32)((64 * nw + 16 * n2 + brow) * 256);

    #pragma unroll 1
    for (int ks = 0; ks < 8; ks++) {
        const int kc0 = ks * 2;
        const u32 axor = (u32)(((kc0 + akl) ^ lr) << 4);
        const u32 bxor = (u32)(((kc0 + bkl) ^ lr) << 4);
        u32 ah[2][4], b[4][4];
        #pragma unroll
        for (int mt = 0; mt < 2; mt++) ldm_x4(sA + aoffm[mt] + axor, ah[mt]);
        #pragma unroll
        for (int n2 = 0; n2 < 4; n2++) ldm_x4(sB + boff[n2] + bxor, b[n2]);
        #pragma unroll
        for (int mt = 0; mt < 2; mt++)
            #pragma unroll
            for (int nt = 0; nt < 8; nt++)
                mma_f16(acc[mt][nt], ah[mt], &b[nt >> 1][(nt & 1) * 2]);
    }
}

// ---------------- proj: P, Vh, Q in one persistent kernel ----------------------
__global__ void __launch_bounds__(256, 2) proj_kernel(
    const float* __restrict__ V, const int* __restrict__ gidx,
    const float* __restrict__ W1, const float* __restrict__ b1,
    int n_videos, int n_nodes, int p_tiles, int q_tiles)
{
    extern __shared__ char smc[];
    u32 sb = smem_u32(smc);
    const int t = threadIdx.x, w = t >> 5, lane = t & 31;
    const int mw = w >> 1, nw = w & 1;
    const int rr = t >> 2, cc4 = t & 3;

    build_wimg(smc + PP_B0, W1, t);
    build_wimg(smc + PP_B1, W1 + D * D, t);
    if (t < D) ((float*)(smc + PP_BS))[t] = b1[t];

    const float4* V4 = (const float4*)V;
    uint4* Vh4 = (uint4*)g_Vh;
    const int n_total = p_tiles + q_tiles;

    for (int it = blockIdx.x; it < n_total; it += gridDim.x) {
        const int mode = (it >= p_tiles);
        const int tile = mode ? (it - p_tiles) : it;
        const int n_rows = mode ? n_nodes : n_videos;
        __syncthreads();
        #pragma unroll
        for (int h = 0; h < 2; h++) {
            int r = 64 * h + rr;
            int gr = tile * 128 + r; if (gr >= n_rows) gr = n_rows - 1;
            int src = mode ? gidx[gr] : gr;
            const float4* Vr = V4 + (size_t)src * 32;
            #pragma unroll
            for (int m = 0; m < 4; m++) {
                int j = cc4 + 4 * m;
                uint4 hv = pack8h(Vr[2 * j], Vr[2 * j + 1]);
                u32 off = (u32)(r * 256 + ((j ^ (r & 7)) << 4));
                *(uint4*)(smc + PP_A + off) = hv;
                if (!mode) Vh4[(size_t)gr * 16 + j] = hv;
            }
        }
        __syncthreads();

        float acc[2][8][4];
        #pragma unroll
        for (int a = 0; a < 2; a++)
            #pragma unroll
            for (int b = 0; b < 8; b++)
                #pragma unroll
                for (int c = 0; c < 4; c++) acc[a][b][c] = 0.f;
        gemm32_1p(sb + PP_A, sb + (mode ? PP_B1 : PP_B0), lane, mw, nw, acc);

        const float* b1s = (const float*)(smc + PP_BS);
        #pragma unroll
        for (int mt = 0; mt < 2; mt++)
            #pragma unroll
            for (int nt = 0; nt < 8; nt++) {
                int gr0 = tile * 128 + 32 * mw + 16 * mt + (lane >> 2);
                int gc = 64 * nw + 8 * nt + 2 * (lane & 3);
                float bx = mode ? b1s[gc] : 0.f;
                float by = mode ? b1s[gc + 1] : 0.f;
                __half2 ha = __floats2half2_rn(acc[mt][nt][0] + bx, acc[mt][nt][1] + by);
                __half2 hb = __floats2half2_rn(acc[mt][nt][2] + bx, acc[mt][nt][3] + by);
                u32* dst = mode ? (u32*)g_Qh : (u32*)g_Ph;
                if (gr0 < n_rows)     dst[(size_t)gr0 * 64 + (gc >> 1)] = *(u32*)&ha;
                if (gr0 + 8 < n_rows) dst[(size_t)(gr0 + 8) * 64 + (gc >> 1)] = *(u32*)&hb;
            }
    }
}

// ---------------- agg: M=128 (4 nodes), P staged via cp.async one tile ahead ---
__global__ void __launch_bounds__(256, 2) agg_kernel(
    const int* __restrict__ neigh, const float* __restrict__ W2,
    const float* __restrict__ b2, const float* __restrict__ W3,
    float* __restrict__ out, int n_nodes, int n_tiles)
{
    extern __shared__ char smc[];
    u32 sb = smem_u32(smc);
    const int t = threadIdx.x, w = t >> 5, lane = t & 31;
    const int mw = w >> 1, nw = w & 1;
    const int rr = t >> 2, cc4 = t & 3;
    const int srow = t >> 1, shalf = (t & 1) * 128;   // P-staging row / half-row

    float2* b2w3  = (float2*)(smc + AG_BW);
    uint4*  qst   = (uint4*)(smc + AG_QST);    // [2buf][64]
    int*    idx_s = (int*)(smc + AG_IDX);      // [2buf][128]
    float*  spart = (float*)(smc + AG_SP);     // [2][128]
    float*  att   = (float*)(smc + AG_ATT);    // [128]
    float4* pp4   = (float4*)(smc + AG_A);     // partials overlay (post-GEMM)

    build_wimg(smc + AG_B, W2, t);
    if (t < D) b2w3[t] = make_float2(b2[t], W3[t]);

    const uint4* Vh4 = (const uint4*)g_Vh;
    const uint4* Qh4 = (const uint4*)g_Qh;
    const int idx_max = n_nodes * 32 - 1;

    {   // prologue: idx/Q for tile0 (buf0) and tile1 (buf1); stage P(tile0)
        int tile0 = blockIdx.x; if (tile0 >= n_tiles) tile0 = n_tiles - 1;
        int tile1 = tile0 + gridDim.x; if (tile1 >= n_tiles) tile1 = tile0;
        if (t < 128) {
            int gi0 = tile0 * 128 + t; if (gi0 > idx_max) gi0 = idx_max;
            int gi1 = tile1 * 128 + t; if (gi1 > idx_max) gi1 = idx_max;
            idx_s[t] = neigh[gi0];
            idx_s[128 + t] = neigh[gi1];
        }
        if (t < 64) {
            int q0 = 4 * tile0 + (t >> 4); if (q0 >= n_nodes) q0 = n_nodes - 1;
            int q1 = 4 * tile1 + (t >> 4); if (q1 >= n_nodes) q1 = n_nodes - 1;
            qst[t]      = Qh4[(size_t)q0 * 16 + (t & 15)];
            qst[64 + t] = Qh4[(size_t)q1 * 16 + (t & 15)];
        }
        __syncthreads();
        int vid = idx_s[srow];
        const char* src = (const char*)g_Ph + (size_t)vid * 256 + shalf;
        u32 dst = sb + AG_PST + (u32)(srow * 272 + shalf);
        #pragma unroll
        for (int i = 0; i < 8; i++) cpa16(dst + i * 16, src + i * 16);
        CP_COMMIT();
    }
    int bp = 0;

    for (int tile = blockIdx.x; tile < n_tiles; tile += gridDim.x) {
        const int cur = bp, nxt = bp ^ 1;

        CP_WAIT0(); __syncthreads();   // P(t) landed in PST; pp4 reads (t-1) done

        // convert: A = hmax2(hadd2(PST, Qh), 0) -- smem-only inputs
        #pragma unroll
        for (int h = 0; h < 2; h++) {
            int r = 64 * h + rr;
            const uint4* Pr = (const uint4*)(smc + AG_PST + r * 272);
            const uint4* Qr = qst + cur * 64 + (r >> 5) * 16;
            #pragma unroll
            for (int m = 0; m < 4; m++) {
                int j = cc4 + 4 * m;
                uint4 p = Pr[j], q = Qr[j];
                uint4 o;
                o.x = haddrelu2(p.x, q.x); o.y = haddrelu2(p.y, q.y);
                o.z = haddrelu2(p.z, q.z); o.w = haddrelu2(p.w, q.w);
                u32 off = (u32)(r * 256 + ((j ^ (r & 7)) << 4));
                *(uint4*)(smc + AG_A + off) = o;
            }
        }
        __syncthreads();   // A ready; PST free

        // issue cp.async stage of P(t+1) (indices already resident in idx_s[nxt])
        {
            int vid = idx_s[nxt * 128 + srow];
            const char* src = (const char*)g_Ph + (size_t)vid * 256 + shalf;
            u32 dst = sb + AG_PST + (u32)(srow * 272 + shalf);
            #pragma unroll
            for (int i = 0; i < 8; i++) cpa16(dst + i * 16, src + i * 16);
            CP_COMMIT();
        }

        float acc[2][8][4];
        #pragma unroll
        for (int a = 0; a < 2; a++)
            #pragma unroll
            for (int b = 0; b < 8; b++)
                #pragma unroll
                for (int c = 0; c < 4; c++) acc[a][b][c] = 0.f;
        gemm32_1p(sb + AG_A, sb + AG_B, lane, mw, nw, acc);

        // scores: s[row] = sum_c relu(h2 + b2) * W3
        #pragma unroll
        for (int mt = 0; mt < 2; mt++) {
            float sp0 = 0.f, sp1 = 0.f;
            #pragma unroll
            for (int nt = 0; nt < 8; nt++) {
                int gc = 64 * nw + 8 * nt + 2 * (lane & 3);
                float2 bw0 = b2w3[gc], bw1 = b2w3[gc + 1];
                sp0 += fmaxf(acc[mt][nt][0] + bw0.x, 0.f) * bw0.y + fmaxf(acc[mt][nt][1] + bw1.x, 0.f) * bw1.y;
                sp1 += fmaxf(acc[mt][nt][2] + bw0.x, 0.f) * bw0.y + fmaxf(acc[mt][nt][3] + bw1.x, 0.f) * bw1.y;
            }
            sp0 += __shfl_xor_sync(0xffffffffu, sp0, 1); sp0 += __shfl_xor_sync(0xffffffffu, sp0, 2);
            sp1 += __shfl_xor_sync(0xffffffffu, sp1, 1); sp1 += __shfl_xor_sync(0xffffffffu, sp1, 2);
            if ((lane & 3) == 0) {
                spart[nw * 128 + 32 * mw + 16 * mt + (lane >> 2)]     = sp0;
                spart[nw * 128 + 32 * mw + 16 * mt + 8 + (lane >> 2)] = sp1;
            }
        }
        __syncthreads();   // spart ready; GEMM reads done (A reusable)

        if (w < 4) {       // softmax: warp w = node-local w
            float s = spart[32 * w + lane] + spart[128 + 32 * w + lane];
            float m = s;
            #pragma unroll
            for (int o = 16; o > 0; o >>= 1) m = fmaxf(m, __shfl_xor_sync(0xffffffffu, m, o));
            float ev = expf(s - m);
            float sum = ev;
            #pragma unroll
            for (int o = 16; o > 0; o >>= 1) sum += __shfl_xor_sync(0xffffffffu, sum, o);
            att[32 * w + lane] = ev / sum;
        }
        __syncthreads();

        // aggregate from fp16 V: thread = (node, k-quarter, 8-col chunk)
        {
            int nd = t >> 6, kq = (t >> 4) & 3, c8 = t & 15;
            float a8[8];
            #pragma unroll
            for (int i = 0; i < 8; i++) a8[i] = 0.f;
            #pragma unroll
            for (int kk = 0; kk < 8; kk++) {
                int k = 32 * nd + 8 * kq + kk;
                float a = att[k];
                int vid = idx_s[cur * 128 + k];
                uint4 v = Vh4[(size_t)vid * 16 + c8];
                float2 f0 = __half22float2(*(__half2*)&v.x);
                float2 f1 = __half22float2(*(__half2*)&v.y);
                float2 f2 = __half22float2(*(__half2*)&v.z);
                float2 f3 = __half22float2(*(__half2*)&v.w);
                a8[0] = fmaf(a, f0.x, a8[0]); a8[1] = fmaf(a, f0.y, a8[1]);
                a8[2] = fmaf(a, f1.x, a8[2]); a8[3] = fmaf(a, f1.y, a8[3]);
                a8[4] = fmaf(a, f2.x, a8[4]); a8[5] = fmaf(a, f2.y, a8[5]);
                a8[6] = fmaf(a, f3.x, a8[6]); a8[7] = fmaf(a, f3.y, a8[7]);
            }
            pp4[(nd * 4 + kq) * 32 + c8 * 2]     = make_float4(a8[0], a8[1], a8[2], a8[3]);
            pp4[(nd * 4 + kq) * 32 + c8 * 2 + 1] = make_float4(a8[4], a8[5], a8[6], a8[7]);
        }
        __syncthreads();   // pp4 ready; idx_s[cur] reads done

        // reduce + store out, and prefetch idx/Q for tile t+2 into cur slots
        if (t < 128) {
            int nd = t >> 5, c4 = t & 31;
            float4 s0 = pp4[(nd * 4 + 0) * 32 + c4];
            float4 s1 = pp4[(nd * 4 + 1) * 32 + c4];
            float4 s2 = pp4[(nd * 4 + 2) * 32 + c4];
            float4 s3 = pp4[(nd * 4 + 3) * 32 + c4];
            float4 rv = make_float4(s0.x + s1.x + s2.x + s3.x, s0.y + s1.y + s2.y + s3.y,
                                    s0.z + s1.z + s2.z + s3.z, s0.w + s1.w + s2.w + s3.w);
            int ng = 4 * tile + nd;
            if (ng < n_nodes) ((float4*)out)[(size_t)ng * 32 + c4] = rv;
        }
        {
            int t2 = tile + 2 * gridDim.x;
            if (t2 >= n_tiles) t2 = (tile + gridDim.x < n_tiles) ? tile + gridDim.x : tile;
            if (t < 128) {
                int gi = t2 * 128 + t; if (gi > idx_max) gi = idx_max;
                idx_s[cur * 128 + t] = neigh[gi];
            }
            if (t < 64) {
                int qr = 4 * t2 + (t >> 4); if (qr >= n_nodes) qr = n_nodes - 1;
                qst[cur * 64 + t] = Qh4[(size_t)qr * 16 + (t & 15)];
            }
        }
        // (loop-top CP_WAIT0 + __syncthreads orders pp4 reads vs next A writes)

        bp ^= 1;
    }
}

// -------------------------------------------------------------------------------
extern "C" void kernel_launch(void* const* d_in, const int* in_sizes, int n_in,
                              void* d_out, int out_size)
{
    const float* V     = (const float*)d_in[0];
    const int*   nodes = (const int*)  d_in[1];
    const int*   neigh = (const int*)  d_in[2];
    const float* W1    = (const float*)d_in[3];
    const float* b1    = (const float*)d_in[4];
    const float* W2    = (const float*)d_in[5];
    const float* b2    = (const float*)d_in[6];
    const float* W3    = (const float*)d_in[7];
    float* out = (float*)d_out;

    const int n_videos = in_sizes[0] / D;
    const int n_nodes  = in_sizes[1];
    const int p_tiles  = (n_videos + 127) / 128;
    const int q_tiles  = (n_nodes + 127) / 128;
    const int a_tiles  = (n_nodes + 3) / 4;

    cudaFuncSetAttribute(proj_kernel, cudaFuncAttributeMaxDynamicSharedMemorySize, PP_SMEM);
    cudaFuncSetAttribute(agg_kernel,  cudaFuncAttributeMaxDynamicSharedMemorySize, AG_SMEM);

    proj_kernel<<<296, 256, PP_SMEM>>>(V, nodes, W1, b1, n_videos, n_nodes, p_tiles, q_tiles);
    agg_kernel<<<296, 256, AG_SMEM>>>(neigh, W2, b2, W3, out, n_nodes, a_tiles);
}

// round 12
// speedup vs baseline: 1.2179x; 1.2179x over previous
#include <cuda_runtime.h>
#include <cuda_fp16.h>
#include <cstdint>

#define D 128
#define NV_MAX 200000
#define NN_MAX 20000

typedef unsigned long long u64;
typedef unsigned int u32;

// ---------------- device scratch (no allocs allowed) ------------------------
__device__ __align__(16) unsigned char g_Ph[(size_t)NV_MAX * 256]; // P fp16 (51MB)
__device__ __align__(16) unsigned char g_Vh[(size_t)NV_MAX * 256]; // V fp16 (51MB)
__device__ __align__(16) unsigned char g_Qh[(size_t)NN_MAX * 256]; // Q fp16 (5MB)

// ---------------- smem layouts ------------------------------------------------
// proj (97KB -> 2 CTAs/SM)
#define PP_B0   0
#define PP_B1   32768
#define PP_A    65536
#define PP_BS   98304      // float b1 [128]
#define PP_SMEM 99328
// agg (~70KB -> 2 CTAs/SM)
#define AG_B    0          // B fp16 32K
#define AG_A    32768      // A fp16 32K (overlay: agg partials post-GEMM)
#define AG_BW   65536      // float2 b2/W3 [128]          (1K)
#define AG_QST  66560      // uint4 q rows [2buf][64]     (2K)
#define AG_IDX  68608      // int [2buf][128]             (1K)
#define AG_SP   69632      // score partials float[2][128](1K)
#define AG_SMEM 70656

// ---------------- helpers ------------------------------------------------------
__device__ __forceinline__ u32 smem_u32(const void* p) {
    u32 a; asm("{ .reg .u64 t; cvta.to.shared.u64 t, %1; cvt.u32.u64 %0, t; }" : "=r"(a) : "l"(p));
    return a;
}
__device__ __forceinline__ void ldm_x4(u32 addr, u32* r) {
    asm volatile("ldmatrix.sync.aligned.m8n8.x4.shared.b16 {%0,%1,%2,%3}, [%4];"
        : "=r"(r[0]), "=r"(r[1]), "=r"(r[2]), "=r"(r[3]) : "r"(addr));
}
__device__ __forceinline__ void mma_f16(float* c, const u32* a, const u32* b) {
    asm volatile("mma.sync.aligned.m16n8k16.row.col.f32.f16.f16.f32 "
        "{%0,%1,%2,%3}, {%4,%5,%6,%7}, {%8,%9}, {%0,%1,%2,%3};"
        : "+f"(c[0]), "+f"(c[1]), "+f"(c[2]), "+f"(c[3])
        : "r"(a[0]), "r"(a[1]), "r"(a[2]), "r"(a[3]), "r"(b[0]), "r"(b[1]));
}
__device__ __forceinline__ void prefetch_l1(const void* p) {
    asm volatile("prefetch.global.L1 [%0];" :: "l"(p));
}
__device__ __forceinline__ uint4 pack8h(float4 a, float4 b) {
    __half2 h0 = __floats2half2_rn(a.x, a.y);
    __half2 h1 = __floats2half2_rn(a.z, a.w);
    __half2 h2 = __floats2half2_rn(b.x, b.y);
    __half2 h3 = __floats2half2_rn(b.z, b.w);
    return make_uint4(*(u32*)&h0, *(u32*)&h1, *(u32*)&h2, *(u32*)&h3);
}
// relu(a + b) in packed half2 (u32-typed)
__device__ __forceinline__ u32 haddrelu2(u32 a, u32 b) {
    __half2 s = __hadd2(*(__half2*)&a, *(__half2*)&b);
    u32 zero = 0u;
    __half2 r = __hmax2(s, *(__half2*)&zero);
    return *(u32*)&r;
}
// stage a fp16 transposed+swizzled weight image from fp32 W[k*D+n]
__device__ __forceinline__ void build_wimg(char* dst, const float* __restrict__ W, int t) {
    int n = t & 127, kh = t >> 7;
    #pragma unroll 8
    for (int kk = 0; kk < 64; kk++) {
        int k = kh * 64 + kk;
        __half h = __float2half_rn(W[k * D + n]);
        int o = n * 256 + ((((k >> 3) ^ (n & 7))) << 4) + ((k & 7) << 1);
        *(__half*)(dst + o) = h;
    }
}

// ---------------- GEMM: block 128x128, warp 32x64, fp16 single-pass ------------
__device__ __forceinline__ void gemm32_1p(u32 sA, u32 sB, int lane, int mw, int nw,
                                          float (&acc)[2][8][4]) {
    const int lr   = lane & 7;
    const int akl  = lane >> 4;
    const int arow = lr + ((lane >> 3) & 1) * 8;
    const int bkl  = (lane >> 3) & 1;
    const int brow = lr + (lane >> 4) * 8;
    u32 aoffm[2];
    #pragma unroll
    for (int mt = 0; mt < 2; mt++) aoffm[mt] = (u32)((32 * mw + 16 * mt + arow) * 256);
    u32 boff[4];
    #pragma unroll
    for (int n2 = 0; n2 < 4; n2++) boff[n2] = (u32)((64 * nw + 16 * n2 + brow) * 256);

    #pragma unroll 1
    for (int ks = 0; ks < 8; ks++) {
        const int kc0 = ks * 2;
        const u32 axor = (u32)(((kc0 + akl) ^ lr) << 4);
        const u32 bxor = (u32)(((kc0 + bkl) ^ lr) << 4);
        u32 ah[2][4], b[4][4];
        #pragma unroll
        for (int mt = 0; mt < 2; mt++) ldm_x4(sA + aoffm[mt] + axor, ah[mt]);
        #pragma unroll
        for (int n2 = 0; n2 < 4; n2++) ldm_x4(sB + boff[n2] + bxor, b[n2]);
        #pragma unroll
        for (int mt = 0; mt < 2; mt++)
            #pragma unroll
            for (int nt = 0; nt < 8; nt++)
                mma_f16(acc[mt][nt], ah[mt], &b[nt >> 1][(nt & 1) * 2]);
    }
}

// ---------------- proj: P, Vh, Q in one persistent kernel ----------------------
__global__ void __launch_bounds__(256, 2) proj_kernel(
    const float* __restrict__ V, const int* __restrict__ gidx,
    const float* __restrict__ W1, const float* __restrict__ b1,
    int n_videos, int n_nodes, int p_tiles, int q_tiles)
{
    extern __shared__ char smc[];
    u32 sb = smem_u32(smc);
    const int t = threadIdx.x, w = t >> 5, lane = t & 31;
    const int mw = w >> 1, nw = w & 1;
    const int rr = t >> 2, cc4 = t & 3;

    build_wimg(smc + PP_B0, W1, t);
    build_wimg(smc + PP_B1, W1 + D * D, t);
    if (t < D) ((float*)(smc + PP_BS))[t] = b1[t];

    const float4* V4 = (const float4*)V;
    uint4* Vh4 = (uint4*)g_Vh;
    const int n_total = p_tiles + q_tiles;

    for (int it = blockIdx.x; it < n_total; it += gridDim.x) {
        const int mode = (it >= p_tiles);
        const int tile = mode ? (it - p_tiles) : it;
        const int n_rows = mode ? n_nodes : n_videos;
        __syncthreads();
        #pragma unroll
        for (int h = 0; h < 2; h++) {
            int r = 64 * h + rr;
            int gr = tile * 128 + r; if (gr >= n_rows) gr = n_rows - 1;
            int src = mode ? gidx[gr] : gr;
            const float4* Vr = V4 + (size_t)src * 32;
            #pragma unroll
            for (int m = 0; m < 4; m++) {
                int j = cc4 + 4 * m;
                uint4 hv = pack8h(Vr[2 * j], Vr[2 * j + 1]);
                u32 off = (u32)(r * 256 + ((j ^ (r & 7)) << 4));
                *(uint4*)(smc + PP_A + off) = hv;
                if (!mode) Vh4[(size_t)gr * 16 + j] = hv;
            }
        }
        __syncthreads();

        float acc[2][8][4];
        #pragma unroll
        for (int a = 0; a < 2; a++)
            #pragma unroll
            for (int b = 0; b < 8; b++)
                #pragma unroll
                for (int c = 0; c < 4; c++) acc[a][b][c] = 0.f;
        gemm32_1p(sb + PP_A, sb + (mode ? PP_B1 : PP_B0), lane, mw, nw, acc);

        const float* b1s = (const float*)(smc + PP_BS);
        #pragma unroll
        for (int mt = 0; mt < 2; mt++)
            #pragma unroll
            for (int nt = 0; nt < 8; nt++) {
                int gr0 = tile * 128 + 32 * mw + 16 * mt + (lane >> 2);
                int gc = 64 * nw + 8 * nt + 2 * (lane & 3);
                float bx = mode ? b1s[gc] : 0.f;
                float by = mode ? b1s[gc + 1] : 0.f;
                __half2 ha = __floats2half2_rn(acc[mt][nt][0] + bx, acc[mt][nt][1] + by);
                __half2 hb = __floats2half2_rn(acc[mt][nt][2] + bx, acc[mt][nt][3] + by);
                u32* dst = mode ? (u32*)g_Qh : (u32*)g_Ph;
                if (gr0 < n_rows)     dst[(size_t)gr0 * 64 + (gc >> 1)] = *(u32*)&ha;
                if (gr0 + 8 < n_rows) dst[(size_t)(gr0 + 8) * 64 + (gc >> 1)] = *(u32*)&hb;
            }
    }
}

// ---------------- agg: M=128 (4 nodes), all-fp16, prefetch + fused softmax -----
__global__ void __launch_bounds__(256, 2) agg_kernel(
    const int* __restrict__ neigh, const float* __restrict__ W2,
    const float* __restrict__ b2, const float* __restrict__ W3,
    float* __restrict__ out, int n_nodes, int n_tiles)
{
    extern __shared__ char smc[];
    u32 sb = smem_u32(smc);
    const int t = threadIdx.x, w = t >> 5, lane = t & 31;
    const int mw = w >> 1, nw = w & 1;
    const int rr = t >> 2, cc4 = t & 3;

    float2* b2w3  = (float2*)(smc + AG_BW);
    uint4*  qst   = (uint4*)(smc + AG_QST);    // [2buf][64]
    int*    idx_s = (int*)(smc + AG_IDX);      // [2buf][128]
    float*  spart = (float*)(smc + AG_SP);     // [2][128]
    float4* pp4   = (float4*)(smc + AG_A);     // partials overlay (post-GEMM)

    build_wimg(smc + AG_B, W2, t);
    if (t < D) b2w3[t] = make_float2(b2[t], W3[t]);

    const uint4* Ph4 = (const uint4*)g_Ph;
    const uint4* Vh4 = (const uint4*)g_Vh;
    const uint4* Qh4 = (const uint4*)g_Qh;
    const int idx_max = n_nodes * 32 - 1;

    {   // prologue: idx + Q for first tile into buffer 0
        int tile0 = blockIdx.x; if (tile0 >= n_tiles) tile0 = n_tiles - 1;
        if (t < 128) {
            int gi = tile0 * 128 + t; if (gi > idx_max) gi = idx_max;
            idx_s[t] = neigh[gi];
        }
        if (t < 64) {
            int qr = 4 * tile0 + (t >> 4); if (qr >= n_nodes) qr = n_nodes - 1;
            qst[t] = Qh4[(size_t)qr * 16 + (t & 15)];
        }
    }
    __syncthreads();
    int bp = 0;

    for (int tile = blockIdx.x; tile < n_tiles; tile += gridDim.x) {
        const int cur = bp, nxt = bp ^ 1;

        // convert: A = hmax2(hadd2(Ph[vid], Qh[node]), 0)
        #pragma unroll
        for (int h = 0; h < 2; h++) {
            int r = 64 * h + rr;
            int vid = idx_s[cur * 128 + r];
            const uint4* Pr = Ph4 + (size_t)vid * 16;
            const uint4* Qr = qst + cur * 64 + (r >> 5) * 16;
            #pragma unroll
            for (int m = 0; m < 4; m++) {
                int j = cc4 + 4 * m;
                uint4 p = Pr[j], q = Qr[j];
                uint4 o;
                o.x = haddrelu2(p.x, q.x); o.y = haddrelu2(p.y, q.y);
                o.z = haddrelu2(p.z, q.z); o.w = haddrelu2(p.w, q.w);
                u32 off = (u32)(r * 256 + ((j ^ (r & 7)) << 4));
                *(uint4*)(smc + AG_A + off) = o;
            }
        }
        __syncthreads();   // A ready

        // prefetch V(t) rows into L1 (consumed by aggregate, ~3k cyc away)
        {
            int vid = idx_s[cur * 128 + (t >> 1)];
            prefetch_l1((const char*)g_Vh + (size_t)vid * 256 + (t & 1) * 128);
        }
        // prefetch next tile's idx + Q (hidden by GEMM)
        int tnext = tile + gridDim.x; if (tnext >= n_tiles) tnext = tile;
        if (t < 128) {
            int gi = tnext * 128 + t; if (gi > idx_max) gi = idx_max;
            idx_s[nxt * 128 + t] = neigh[gi];
        }
        if (t < 64) {
            int qr = 4 * tnext + (t >> 4); if (qr >= n_nodes) qr = n_nodes - 1;
            qst[nxt * 64 + t] = Qh4[(size_t)qr * 16 + (t & 15)];
        }

        float acc[2][8][4];
        #pragma unroll
        for (int a = 0; a < 2; a++)
            #pragma unroll
            for (int b = 0; b < 8; b++)
                #pragma unroll
                for (int c = 0; c < 4; c++) acc[a][b][c] = 0.f;
        gemm32_1p(sb + AG_A, sb + AG_B, lane, mw, nw, acc);

        // scores: s[row] = sum_c relu(h2 + b2) * W3
        #pragma unroll
        for (int mt = 0; mt < 2; mt++) {
            float sp0 = 0.f, sp1 = 0.f;
            #pragma unroll
            for (int nt = 0; nt < 8; nt++) {
                int gc = 64 * nw + 8 * nt + 2 * (lane & 3);
                float2 bw0 = b2w3[gc], bw1 = b2w3[gc + 1];
                sp0 += fmaxf(acc[mt][nt][0] + bw0.x, 0.f) * bw0.y + fmaxf(acc[mt][nt][1] + bw1.x, 0.f) * bw1.y;
                sp1 += fmaxf(acc[mt][nt][2] + bw0.x, 0.f) * bw0.y + fmaxf(acc[mt][nt][3] + bw1.x, 0.f) * bw1.y;
            }
            sp0 += __shfl_xor_sync(0xffffffffu, sp0, 1); sp0 += __shfl_xor_sync(0xffffffffu, sp0, 2);
            sp1 += __shfl_xor_sync(0xffffffffu, sp1, 1); sp1 += __shfl_xor_sync(0xffffffffu, sp1, 2);
            if ((lane & 3) == 0) {
                spart[nw * 128 + 32 * mw + 16 * mt + (lane >> 2)]     = sp0;
                spart[nw * 128 + 32 * mw + 16 * mt + 8 + (lane >> 2)] = sp1;
            }
        }
        __syncthreads();   // spart ready; GEMM reads done (A reusable); idx_s[nxt] visible

        // prefetch P(t+1) rows into L1 (consumed by next convert, ~2k cyc away)
        {
            int vid = idx_s[nxt * 128 + (t >> 1)];
            prefetch_l1((const char*)g_Ph + (size_t)vid * 256 + (t & 1) * 128);
        }

        // fused softmax (every warp, redundant per node) + aggregate
        {
            const int nd = w >> 1;                 // node-local, matches aggregate map
            float s = spart[32 * nd + lane] + spart[128 + 32 * nd + lane];
            float m = s;
            #pragma unroll
            for (int o = 16; o > 0; o >>= 1) m = fmaxf(m, __shfl_xor_sync(0xffffffffu, m, o));
            float ev = expf(s - m);
            float sum = ev;
            #pragma unroll
            for (int o = 16; o > 0; o >>= 1) sum += __shfl_xor_sync(0xffffffffu, sum, o);
            float att_r = ev / sum;                // lane l = att of neighbor l (node nd)

            int kq = (t >> 4) & 3, c8 = t & 15;
            float a8[8];
            #pragma unroll
            for (int i = 0; i < 8; i++) a8[i] = 0.f;
            #pragma unroll
            for (int kk = 0; kk < 8; kk++) {
                int kl = 8 * kq + kk;              // neighbor within node
                float a = __shfl_sync(0xffffffffu, att_r, kl & 31);
                int vid = idx_s[cur * 128 + 32 * nd + kl];
                uint4 v = Vh4[(size_t)vid * 16 + c8];
                float2 f0 = __half22float2(*(__half2*)&v.x);
                float2 f1 = __half22float2(*(__half2*)&v.y);
                float2 f2 = __half22float2(*(__half2*)&v.z);
                float2 f3 = __half22float2(*(__half2*)&v.w);
                a8[0] = fmaf(a, f0.x, a8[0]); a8[1] = fmaf(a, f0.y, a8[1]);
                a8[2] = fmaf(a, f1.x, a8[2]); a8[3] = fmaf(a, f1.y, a8[3]);
                a8[4] = fmaf(a, f2.x, a8[4]); a8[5] = fmaf(a, f2.y, a8[5]);
                a8[6] = fmaf(a, f3.x, a8[6]); a8[7] = fmaf(a, f3.y, a8[7]);
            }
            pp4[(nd * 4 + kq) * 32 + c8 * 2]     = make_float4(a8[0], a8[1], a8[2], a8[3]);
            pp4[(nd * 4 + kq) * 32 + c8 * 2 + 1] = make_float4(a8[4], a8[5], a8[6], a8[7]);
        }
        __syncthreads();
        if (t < 128) {
            int nd = t >> 5, c4 = t & 31;
            float4 s0 = pp4[(nd * 4 + 0) * 32 + c4];
            float4 s1 = pp4[(nd * 4 + 1) * 32 + c4];
            float4 s2 = pp4[(nd * 4 + 2) * 32 + c4];
            float4 s3 = pp4[(nd * 4 + 3) * 32 + c4];
            float4 rv = make_float4(s0.x + s1.x + s2.x + s3.x, s0.y + s1.y + s2.y + s3.y,
                                    s0.z + s1.z + s2.z + s3.z, s0.w + s1.w + s2.w + s3.w);
            int ng = 4 * tile + nd;
            if (ng < n_nodes) ((float4*)out)[(size_t)ng * 32 + c4] = rv;
        }
        __syncthreads();   // pp4 reads done before next convert overwrites A

        bp ^= 1;
    }
}

// -------------------------------------------------------------------------------
extern "C" void kernel_launch(void* const* d_in, const int* in_sizes, int n_in,
                              void* d_out, int out_size)
{
    const float* V     = (const float*)d_in[0];
    const int*   nodes = (const int*)  d_in[1];
    const int*   neigh = (const int*)  d_in[2];
    const float* W1    = (const float*)d_in[3];
    const float* b1    = (const float*)d_in[4];
    const float* W2    = (const float*)d_in[5];
    const float* b2    = (const float*)d_in[6];
    const float* W3    = (const float*)d_in[7];
    float* out = (float*)d_out;

    const int n_videos = in_sizes[0] / D;
    const int n_nodes  = in_sizes[1];
    const int p_tiles  = (n_videos + 127) / 128;
    const int q_tiles  = (n_nodes + 127) / 128;
    const int a_tiles  = (n_nodes + 3) / 4;

    cudaFuncSetAttribute(proj_kernel, cudaFuncAttributeMaxDynamicSharedMemorySize, PP_SMEM);
    cudaFuncSetAttribute(agg_kernel,  cudaFuncAttributeMaxDynamicSharedMemorySize, AG_SMEM);

    proj_kernel<<<296, 256, PP_SMEM>>>(V, nodes, W1, b1, n_videos, n_nodes, p_tiles, q_tiles);
    agg_kernel<<<296, 256, AG_SMEM>>>(neigh, W2, b2, W3, out, n_nodes, a_tiles);
}